// round 5
// baseline (speedup 1.0000x reference)
#include <cuda_runtime.h>
#include <cuda_bf16.h>
#include <math.h>
#include <stdint.h>

#define HID 2048
#define BATCH 512
#define SEQ 128
#define NCLS 10

#define BM 128            // batch rows per CTA
#define BN 64             // hidden cols per CTA
#define KS 64             // k elements per slab
#define NSLAB (HID / KS)  // 32

// ---- device globals (allocation-free scratch) ----
__device__ __nv_bfloat16 g_hTh[2][BATCH * HID];   // hidden hi, [B][K] row-major
__device__ __nv_bfloat16 g_hTl[2][BATCH * HID];   // hidden lo
__device__ __nv_bfloat16 g_Wh[HID * HID];         // whh hi, [N][K] row-major
__device__ __nv_bfloat16 g_Wl[HID * HID];         // whh lo

// ---- SMEM layout (dynamic) ----
#define SM_XS   0                 // 128 f32
#define SM_WHX  512               // 64 f32
#define SM_BH   768               // 64 f32
#define SM_SLAB 1024
#define AH_OFF  0                 // 128 rows x 128B
#define AL_OFF  16384
#define WH_OFF  32768             // 64 rows x 128B
#define WL_OFF  40960
#define STAGE_SZ 49152
#define SMEM_TOTAL (SM_SLAB + 2 * STAGE_SZ)   // 99328
// epilogue k-group reduction area (reuses slab buffers): 4 regions of 64 rows x 136B
#define RED_STRIDE 136
#define RED_REGION (64 * RED_STRIDE)

__device__ __forceinline__ uint32_t smem_u32(const void* p) {
    uint32_t a;
    asm("{ .reg .u64 t; cvta.to.shared.u64 t, %1; cvt.u32.u64 %0, t; }" : "=r"(a) : "l"(p));
    return a;
}
__device__ __forceinline__ void cp16(uint32_t saddr, const void* g) {
    asm volatile("cp.async.cg.shared.global [%0], [%1], 16;" :: "r"(saddr), "l"(g));
}
#define CP_COMMIT() asm volatile("cp.async.commit_group;" ::: "memory")
#define CP_WAIT(n)  asm volatile("cp.async.wait_group %0;" :: "n"(n) : "memory")

#define LDSM_X4(d0, d1, d2, d3, a) \
    asm volatile("ldmatrix.sync.aligned.m8n8.x4.shared.b16 {%0,%1,%2,%3}, [%4];" \
        : "=r"(d0), "=r"(d1), "=r"(d2), "=r"(d3) : "r"(a))

#define MMA16816(c0, c1, c2, c3, a0, a1, a2, a3, b0, b1) \
    asm volatile("mma.sync.aligned.m16n8k16.row.col.f32.bf16.bf16.f32 " \
        "{%0,%1,%2,%3}, {%4,%5,%6,%7}, {%8,%9}, {%0,%1,%2,%3};" \
        : "+f"(c0), "+f"(c1), "+f"(c2), "+f"(c3) \
        : "r"(a0), "r"(a1), "r"(a2), "r"(a3), "r"(b0), "r"(b1))

// ================= one-time prep =================
__global__ __launch_bounds__(256) void convert_w(const float* __restrict__ whh) {
    int i = blockIdx.x * blockDim.x + threadIdx.x;
    if (i >= HID * HID) return;
    float w = whh[i];
    __nv_bfloat16 hi = __float2bfloat16(w);
    g_Wh[i] = hi;
    g_Wl[i] = __float2bfloat16(w - __bfloat162float(hi));
}

__global__ __launch_bounds__(256) void rnn_init(
    const float* __restrict__ whx, const float* __restrict__ bh, const float* __restrict__ x) {
    int i = blockIdx.x * blockDim.x + threadIdx.x;
    if (i >= BATCH * HID) return;
    int b = i / HID, m = i - b * HID;
    float v = tanhf(whx[m] * x[b * SEQ + 0] + bh[m]);
    __nv_bfloat16 hi = __float2bfloat16(v);
    g_hTh[0][i] = hi;
    g_hTl[0][i] = __float2bfloat16(v - __bfloat162float(hi));
}

// ================= per-step GEMM: hT_new = tanh(hT @ W^T + whx*x_t + bh) =================
// 8 warps = 2 k-groups x (2 wm x 2 wn); warp tile 64m x 32n; split-K over slab halves.
__global__ __launch_bounds__(256, 1) void rnn_step_mma(
    const float* __restrict__ x, const float* __restrict__ whx,
    const float* __restrict__ bh, int t, int src, int dst)
{
    extern __shared__ char smem[];
    uint32_t sb = smem_u32(smem);
    int tid = threadIdx.x, wid = tid >> 5, lane = tid & 31;
    int kg = wid >> 2;             // k-group: 0 -> k16 {0,1}, 1 -> k16 {2,3} of each slab
    int wm = (wid >> 1) & 1;       // 64-row group
    int wn = wid & 1;              // 32-col group
    int n0  = blockIdx.x * BN;     // hidden col base
    int bt0 = blockIdx.y * BM;     // batch row base

    if (tid < 128) ((float*)(smem + SM_XS))[tid] = x[(bt0 + tid) * SEQ + t];
    else if (tid < 192) ((float*)(smem + SM_WHX))[tid - 128] = whx[n0 + tid - 128];
    else ((float*)(smem + SM_BH))[tid - 192] = bh[n0 + tid - 192];

    const __nv_bfloat16* Ah = g_hTh[src] + (size_t)bt0 * HID;
    const __nv_bfloat16* Al = g_hTl[src] + (size_t)bt0 * HID;
    const __nv_bfloat16* Wh = g_Wh + (size_t)n0 * HID;
    const __nv_bfloat16* Wl = g_Wl + (size_t)n0 * HID;

    float c[4][4][4];
#pragma unroll
    for (int i = 0; i < 4; i++)
#pragma unroll
        for (int j = 0; j < 4; j++)
#pragma unroll
            for (int q = 0; q < 4; q++) c[i][j][q] = 0.f;

#define LOAD_SLAB(stage, ks) do {                                              \
        uint32_t sbase = sb + SM_SLAB + (stage) * STAGE_SZ;                    \
        _Pragma("unroll")                                                      \
        for (int i = 0; i < 4; i++) {                                          \
            int idx = tid + 256 * i; int m = idx >> 3; int cc = idx & 7;       \
            uint32_t so = (uint32_t)(m * 128) + (uint32_t)((cc ^ (m & 7)) << 4); \
            size_t go = (size_t)m * HID + (ks) * KS + cc * 8;                  \
            cp16(sbase + AH_OFF + so, Ah + go);                                \
            cp16(sbase + AL_OFF + so, Al + go);                                \
        }                                                                      \
        _Pragma("unroll")                                                      \
        for (int i = 0; i < 2; i++) {                                          \
            int idx = tid + 256 * i; int n = idx >> 3; int cc = idx & 7;       \
            uint32_t so = (uint32_t)(n * 128) + (uint32_t)((cc ^ (n & 7)) << 4); \
            size_t go = (size_t)n * HID + (ks) * KS + cc * 8;                  \
            cp16(sbase + WH_OFF + so, Wh + go);                                \
            cp16(sbase + WL_OFF + so, Wl + go);                                \
        }                                                                      \
        CP_COMMIT();                                                           \
    } while (0)

    LOAD_SLAB(0, 0);

#pragma unroll 1
    for (int ks = 0; ks < NSLAB; ks++) {
        if (ks + 1 < NSLAB) {
            LOAD_SLAB((ks + 1) & 1, ks + 1);
            CP_WAIT(1);
        } else {
            CP_WAIT(0);
        }
        __syncthreads();

        uint32_t abase = sb + SM_SLAB + (ks & 1) * STAGE_SZ;
#pragma unroll
        for (int kk = 0; kk < 2; kk++) {
            int cb = (kg * 2 + kk) * 2;   // 16B-chunk base of this k16 within the slab
            uint32_t ah[4][4], al[4][4], wh[2][4], wl[2][4];
#pragma unroll
            for (int mt = 0; mt < 4; mt++) {
                int row = wm * 64 + mt * 16 + (lane & 15);
                int ccc = cb + (lane >> 4);
                uint32_t ad = abase + AH_OFF + row * 128 + ((ccc ^ (row & 7)) << 4);
                LDSM_X4(ah[mt][0], ah[mt][1], ah[mt][2], ah[mt][3], ad);
                LDSM_X4(al[mt][0], al[mt][1], al[mt][2], al[mt][3], ad + (AL_OFF - AH_OFF));
            }
#pragma unroll
            for (int nt = 0; nt < 2; nt++) {
                int row = wn * 32 + nt * 16 + (lane & 7) + ((lane >> 4) << 3);
                int ccc = cb + ((lane >> 3) & 1);
                uint32_t ad = abase + WH_OFF + row * 128 + ((ccc ^ (row & 7)) << 4);
                LDSM_X4(wh[nt][0], wh[nt][1], wh[nt][2], wh[nt][3], ad);
                LDSM_X4(wl[nt][0], wl[nt][1], wl[nt][2], wl[nt][3], ad + (WL_OFF - WH_OFF));
            }
#pragma unroll
            for (int mt = 0; mt < 4; mt++) {
#pragma unroll
                for (int j = 0; j < 4; j++) {
                    uint32_t bh0 = wh[j >> 1][(j & 1) * 2], bh1 = wh[j >> 1][(j & 1) * 2 + 1];
                    uint32_t bl0 = wl[j >> 1][(j & 1) * 2], bl1 = wl[j >> 1][(j & 1) * 2 + 1];
                    MMA16816(c[mt][j][0], c[mt][j][1], c[mt][j][2], c[mt][j][3],
                             ah[mt][0], ah[mt][1], ah[mt][2], ah[mt][3], bh0, bh1);
                    MMA16816(c[mt][j][0], c[mt][j][1], c[mt][j][2], c[mt][j][3],
                             al[mt][0], al[mt][1], al[mt][2], al[mt][3], bh0, bh1);
                    MMA16816(c[mt][j][0], c[mt][j][1], c[mt][j][2], c[mt][j][3],
                             ah[mt][0], ah[mt][1], ah[mt][2], ah[mt][3], bl0, bl1);
                }
            }
        }
        __syncthreads();
    }
#undef LOAD_SLAB

    // ---- cross-k-group reduction via smem (reuses slab buffers) ----
    int g = lane >> 2, tg = lane & 3;
    char* rbase = smem + SM_SLAB + (wm * 2 + wn) * RED_REGION;

    if (kg == 1) {
#pragma unroll
        for (int mt = 0; mt < 4; mt++)
#pragma unroll
            for (int half = 0; half < 2; half++) {
                int rl = mt * 16 + half * 8 + g;
#pragma unroll
                for (int j = 0; j < 4; j++) {
                    float2 v = make_float2(c[mt][j][half * 2], c[mt][j][half * 2 + 1]);
                    *(float2*)(rbase + rl * RED_STRIDE + (j * 8 + 2 * tg) * 4) = v;
                }
            }
    }
    __syncthreads();

    if (kg == 0) {
        const float* xs   = (const float*)(smem + SM_XS);
        const float* whxs = (const float*)(smem + SM_WHX);
        const float* bhs  = (const float*)(smem + SM_BH);
        __nv_bfloat16* Dh = g_hTh[dst];
        __nv_bfloat16* Dl = g_hTl[dst];
#pragma unroll
        for (int mt = 0; mt < 4; mt++) {
#pragma unroll
            for (int half = 0; half < 2; half++) {
                int rl = mt * 16 + half * 8 + g;
                int rloc = wm * 64 + rl;
                float xv = xs[rloc];
                size_t rowbase = (size_t)(bt0 + rloc) * HID + n0;
#pragma unroll
                for (int j = 0; j < 4; j++) {
                    float2 p = *(const float2*)(rbase + rl * RED_STRIDE + (j * 8 + 2 * tg) * 4);
                    int nloc = wn * 32 + j * 8 + 2 * tg;
                    float v0 = c[mt][j][half * 2 + 0] + p.x + whxs[nloc] * xv + bhs[nloc];
                    float v1 = c[mt][j][half * 2 + 1] + p.y + whxs[nloc + 1] * xv + bhs[nloc + 1];
                    float t0 = tanhf(v0), t1 = tanhf(v1);
                    __nv_bfloat16 h0 = __float2bfloat16(t0);
                    __nv_bfloat16 h1 = __float2bfloat16(t1);
                    __nv_bfloat162 hp; hp.x = h0; hp.y = h1;
                    __nv_bfloat162 lp;
                    lp.x = __float2bfloat16(t0 - __bfloat162float(h0));
                    lp.y = __float2bfloat16(t1 - __bfloat162float(h1));
                    *(__nv_bfloat162*)(Dh + rowbase + nloc) = hp;
                    *(__nv_bfloat162*)(Dl + rowbase + nloc) = lp;
                }
            }
        }
    }
}

// ================= final projection =================
__global__ __launch_bounds__(256) void rnn_proj(
    const float* __restrict__ wph, const float* __restrict__ bp,
    float* __restrict__ out, int src)
{
    int b = blockIdx.x;
    int tid = threadIdx.x;
    const __nv_bfloat16* Hh = g_hTh[src] + (size_t)b * HID;
    const __nv_bfloat16* Hl = g_hTl[src] + (size_t)b * HID;

    float acc[NCLS];
#pragma unroll
    for (int c = 0; c < NCLS; c++) acc[c] = 0.f;

    for (int k = tid; k < HID; k += 256) {
        float hv = __bfloat162float(Hh[k]) + __bfloat162float(Hl[k]);
#pragma unroll
        for (int c = 0; c < NCLS; c++)
            acc[c] = fmaf(wph[c * HID + k], hv, acc[c]);
    }

    __shared__ float red[256];
    for (int c = 0; c < NCLS; c++) {
        red[tid] = acc[c];
        __syncthreads();
        for (int s = 128; s > 0; s >>= 1) {
            if (tid < s) red[tid] += red[tid + s];
            __syncthreads();
        }
        if (tid == 0) out[b * NCLS + c] = red[0] + bp[c];
        __syncthreads();
    }
}

extern "C" void kernel_launch(void* const* d_in, const int* in_sizes, int n_in,
                              void* d_out, int out_size) {
    const float* x   = (const float*)d_in[0];    // [512, 128]
    const float* whx = (const float*)d_in[1];    // [2048, 1]
    const float* whh = (const float*)d_in[2];    // [2048, 2048]
    const float* bh  = (const float*)d_in[3];    // [2048, 1]
    const float* wph = (const float*)d_in[4];    // [10, 2048]
    const float* bp  = (const float*)d_in[5];    // [10, 1]
    float* out = (float*)d_out;                  // [512, 10]
    (void)in_sizes; (void)n_in; (void)out_size;

    cudaFuncSetAttribute(rnn_step_mma, cudaFuncAttributeMaxDynamicSharedMemorySize, SMEM_TOTAL);

    convert_w<<<(HID * HID + 255) / 256, 256>>>(whh);
    rnn_init<<<(BATCH * HID + 255) / 256, 256>>>(whx, bh, x);

    dim3 grid(HID / BN, BATCH / BM);  // (32, 4) = 128 CTAs
    for (int t = 1; t < SEQ; t++) {
        rnn_step_mma<<<grid, 256, SMEM_TOTAL>>>(x, whx, bh, t, (t - 1) & 1, t & 1);
    }

    rnn_proj<<<BATCH, 256>>>(wph, bp, out, (SEQ - 1) & 1);  // final h in buf 1
}

// round 6
// speedup vs baseline: 1.0256x; 1.0256x over previous
#include <cuda_runtime.h>
#include <cuda_bf16.h>
#include <math.h>
#include <stdint.h>

#define HID 2048
#define BATCH 512
#define SEQ 128
#define NCLS 10

#define BM 128            // batch rows per CTA
#define BN 64             // hidden cols per CTA
#define KS 64             // k elements per slab
#define NSLAB (HID / KS)  // 32
#define NCTA 128          // grid = 32 x 4

// ---- device globals (allocation-free scratch) ----
__device__ __nv_bfloat16 g_hTh[2][BATCH * HID];   // hidden hi, [B][K] row-major
__device__ __nv_bfloat16 g_hTl[2][BATCH * HID];   // hidden lo
__device__ __nv_bfloat16 g_Wh[HID * HID];         // whh hi, [N][K] row-major
__device__ __nv_bfloat16 g_Wl[HID * HID];         // whh lo
__device__ unsigned g_bar;                        // device-wide step barrier

// ---- SMEM layout (dynamic): 3-stage ring ----
#define SM_XS   0                 // 128 f32
#define SM_WHX  512               // 64 f32
#define SM_BH   768               // 64 f32
#define SM_SLAB 1024
#define AH_OFF  0                 // 128 rows x 128B
#define AL_OFF  16384
#define WH_OFF  32768             // 64 rows x 128B
#define WL_OFF  40960
#define STAGE_SZ 49152
#define SMEM_TOTAL (SM_SLAB + 3 * STAGE_SZ)   // 148480

__device__ __forceinline__ uint32_t smem_u32(const void* p) {
    uint32_t a;
    asm("{ .reg .u64 t; cvta.to.shared.u64 t, %1; cvt.u32.u64 %0, t; }" : "=r"(a) : "l"(p));
    return a;
}
__device__ __forceinline__ void cp16(uint32_t saddr, const void* g) {
    asm volatile("cp.async.cg.shared.global [%0], [%1], 16;" :: "r"(saddr), "l"(g));
}
#define CP_COMMIT() asm volatile("cp.async.commit_group;" ::: "memory")
#define CP_WAIT(n)  asm volatile("cp.async.wait_group %0;" :: "n"(n) : "memory")

#define LDSM_X4(d0, d1, d2, d3, a) \
    asm volatile("ldmatrix.sync.aligned.m8n8.x4.shared.b16 {%0,%1,%2,%3}, [%4];" \
        : "=r"(d0), "=r"(d1), "=r"(d2), "=r"(d3) : "r"(a))

#define MMA16816(c0, c1, c2, c3, a0, a1, a2, a3, b0, b1) \
    asm volatile("mma.sync.aligned.m16n8k16.row.col.f32.bf16.bf16.f32 " \
        "{%0,%1,%2,%3}, {%4,%5,%6,%7}, {%8,%9}, {%0,%1,%2,%3};" \
        : "+f"(c0), "+f"(c1), "+f"(c2), "+f"(c3) \
        : "r"(a0), "r"(a1), "r"(a2), "r"(a3), "r"(b0), "r"(b1))

// ================= one-time prep =================
__global__ __launch_bounds__(256) void convert_w(const float* __restrict__ whh) {
    int i = blockIdx.x * blockDim.x + threadIdx.x;
    if (i >= HID * HID) return;
    float w = whh[i];
    __nv_bfloat16 hi = __float2bfloat16(w);
    g_Wh[i] = hi;
    g_Wl[i] = __float2bfloat16(w - __bfloat162float(hi));
}

__global__ __launch_bounds__(256) void rnn_init(
    const float* __restrict__ whx, const float* __restrict__ bh, const float* __restrict__ x) {
    int i = blockIdx.x * blockDim.x + threadIdx.x;
    if (i == 0) g_bar = 0;  // reset step barrier every replay
    if (i >= BATCH * HID) return;
    int b = i / HID, m = i - b * HID;
    float v = tanhf(whx[m] * x[b * SEQ + 0] + bh[m]);
    __nv_bfloat16 hi = __float2bfloat16(v);
    g_hTh[0][i] = hi;
    g_hTl[0][i] = __float2bfloat16(v - __bfloat162float(hi));
}

// ================= persistent RNN: steps 1..127 in one launch =================
__global__ __launch_bounds__(256, 1) void rnn_persist(
    const float* __restrict__ x, const float* __restrict__ whx,
    const float* __restrict__ bh)
{
    extern __shared__ char smem[];
    uint32_t sb = smem_u32(smem);
    int tid = threadIdx.x, wid = tid >> 5, lane = tid & 31;
    int wm = wid >> 1, wn = wid & 1;      // 4x2 warps, warp tile 32m x 32n
    int n0  = blockIdx.x * BN;            // hidden col base
    int bt0 = blockIdx.y * BM;            // batch row base

    if (tid >= 128 && tid < 192) ((float*)(smem + SM_WHX))[tid - 128] = whx[n0 + tid - 128];
    else if (tid >= 192) ((float*)(smem + SM_BH))[tid - 192] = bh[n0 + tid - 192];

    int g = lane >> 2, tg = lane & 3;

#define LOAD_SLAB(stage, ks) do {                                              \
        uint32_t sbase = sb + SM_SLAB + (stage) * STAGE_SZ;                    \
        _Pragma("unroll")                                                      \
        for (int i = 0; i < 4; i++) {                                          \
            int idx = tid + 256 * i; int m = idx >> 3; int cc = idx & 7;       \
            uint32_t so = (uint32_t)(m * 128) + (uint32_t)((cc ^ (m & 7)) << 4); \
            size_t go = (size_t)m * HID + (ks) * KS + cc * 8;                  \
            cp16(sbase + AH_OFF + so, Ah + go);                                \
            cp16(sbase + AL_OFF + so, Al + go);                                \
        }                                                                      \
        _Pragma("unroll")                                                      \
        for (int i = 0; i < 2; i++) {                                          \
            int idx = tid + 256 * i; int n = idx >> 3; int cc = idx & 7;       \
            uint32_t so = (uint32_t)(n * 128) + (uint32_t)((cc ^ (n & 7)) << 4); \
            size_t go = (size_t)n * HID + (ks) * KS + cc * 8;                  \
            cp16(sbase + WH_OFF + so, Wh + go);                                \
            cp16(sbase + WL_OFF + so, Wl + go);                                \
        }                                                                      \
        CP_COMMIT();                                                           \
    } while (0)

#pragma unroll 1
    for (int t = 1; t < SEQ; t++) {
        int src = (t - 1) & 1, dst = t & 1;
        if (tid < 128) ((float*)(smem + SM_XS))[tid] = x[(bt0 + tid) * SEQ + t];

        const __nv_bfloat16* Ah = g_hTh[src] + (size_t)bt0 * HID;
        const __nv_bfloat16* Al = g_hTl[src] + (size_t)bt0 * HID;
        const __nv_bfloat16* Wh = g_Wh + (size_t)n0 * HID;
        const __nv_bfloat16* Wl = g_Wl + (size_t)n0 * HID;

        float c[2][4][4];
#pragma unroll
        for (int i = 0; i < 2; i++)
#pragma unroll
            for (int j = 0; j < 4; j++)
#pragma unroll
                for (int q = 0; q < 4; q++) c[i][j][q] = 0.f;

        LOAD_SLAB(0, 0);
        LOAD_SLAB(1, 1);

#pragma unroll 1
        for (int ks = 0; ks < NSLAB; ks++) {
            if (ks < NSLAB - 2) { CP_WAIT(1); } else { CP_WAIT(0); }
            __syncthreads();   // slab ks visible; all warps done reading stage (ks+2)%3
            if (ks + 2 < NSLAB) LOAD_SLAB((ks + 2) % 3, ks + 2);

            uint32_t abase = sb + SM_SLAB + (ks % 3) * STAGE_SZ;
#pragma unroll
            for (int k4 = 0; k4 < 4; k4++) {
                int cb = k4 * 2;   // 16B-chunk base of this k16 within the 64-wide slab
                uint32_t ah[2][4], al[2][4], wh[2][4], wl[2][4];
#pragma unroll
                for (int mt = 0; mt < 2; mt++) {
                    int row = wm * 32 + mt * 16 + (lane & 15);
                    int ccc = cb + (lane >> 4);
                    uint32_t ad = abase + AH_OFF + row * 128 + ((ccc ^ (row & 7)) << 4);
                    LDSM_X4(ah[mt][0], ah[mt][1], ah[mt][2], ah[mt][3], ad);
                    LDSM_X4(al[mt][0], al[mt][1], al[mt][2], al[mt][3], ad + (AL_OFF - AH_OFF));
                }
#pragma unroll
                for (int nt = 0; nt < 2; nt++) {
                    int row = wn * 32 + nt * 16 + (lane & 7) + ((lane >> 4) << 3);
                    int ccc = cb + ((lane >> 3) & 1);
                    uint32_t ad = abase + WH_OFF + row * 128 + ((ccc ^ (row & 7)) << 4);
                    LDSM_X4(wh[nt][0], wh[nt][1], wh[nt][2], wh[nt][3], ad);
                    LDSM_X4(wl[nt][0], wl[nt][1], wl[nt][2], wl[nt][3], ad + (WL_OFF - WH_OFF));
                }
#pragma unroll
                for (int mt = 0; mt < 2; mt++) {
#pragma unroll
                    for (int j = 0; j < 4; j++) {
                        uint32_t bh0 = wh[j >> 1][(j & 1) * 2], bh1 = wh[j >> 1][(j & 1) * 2 + 1];
                        uint32_t bl0 = wl[j >> 1][(j & 1) * 2], bl1 = wl[j >> 1][(j & 1) * 2 + 1];
                        MMA16816(c[mt][j][0], c[mt][j][1], c[mt][j][2], c[mt][j][3],
                                 ah[mt][0], ah[mt][1], ah[mt][2], ah[mt][3], bh0, bh1);
                        MMA16816(c[mt][j][0], c[mt][j][1], c[mt][j][2], c[mt][j][3],
                                 al[mt][0], al[mt][1], al[mt][2], al[mt][3], bh0, bh1);
                        MMA16816(c[mt][j][0], c[mt][j][1], c[mt][j][2], c[mt][j][3],
                                 ah[mt][0], ah[mt][1], ah[mt][2], ah[mt][3], bl0, bl1);
                    }
                }
            }
        }

        // ---- epilogue: + whx*x + bh, tanh, bf16 hi/lo split, store ----
        {
            const float* xs   = (const float*)(smem + SM_XS);
            const float* whxs = (const float*)(smem + SM_WHX);
            const float* bhs  = (const float*)(smem + SM_BH);
            __nv_bfloat16* Dh = g_hTh[dst];
            __nv_bfloat16* Dl = g_hTl[dst];
#pragma unroll
            for (int mt = 0; mt < 2; mt++) {
#pragma unroll
                for (int half = 0; half < 2; half++) {
                    int rloc = wm * 32 + mt * 16 + g + half * 8;
                    float xv = xs[rloc];
                    size_t rowbase = (size_t)(bt0 + rloc) * HID + n0;
#pragma unroll
                    for (int j = 0; j < 4; j++) {
                        int nloc = wn * 32 + j * 8 + 2 * tg;
                        float v0 = c[mt][j][half * 2 + 0] + whxs[nloc] * xv + bhs[nloc];
                        float v1 = c[mt][j][half * 2 + 1] + whxs[nloc + 1] * xv + bhs[nloc + 1];
                        float t0 = tanhf(v0), t1 = tanhf(v1);
                        __nv_bfloat16 h0 = __float2bfloat16(t0);
                        __nv_bfloat16 h1 = __float2bfloat16(t1);
                        __nv_bfloat162 hp; hp.x = h0; hp.y = h1;
                        __nv_bfloat162 lp;
                        lp.x = __float2bfloat16(t0 - __bfloat162float(h0));
                        lp.y = __float2bfloat16(t1 - __bfloat162float(h1));
                        *(__nv_bfloat162*)(Dh + rowbase + nloc) = hp;
                        *(__nv_bfloat162*)(Dl + rowbase + nloc) = lp;
                    }
                }
            }
        }

        // ---- device-wide step barrier (all 128 CTAs are co-resident: 1/SM) ----
        if (t < SEQ - 1) {
            __syncthreads();                      // CTA's stores issued
            if (tid == 0) {
                __threadfence();                  // release h stores to gpu scope
                atomicAdd(&g_bar, 1u);
                unsigned tgt = (unsigned)(NCTA * t);
                unsigned cur;
                do {
                    asm volatile("ld.acquire.gpu.b32 %0, [%1];" : "=r"(cur) : "l"(&g_bar));
                } while (cur < tgt);
                __threadfence();                  // acquire for the whole CTA
            }
            __syncthreads();
        }
    }
#undef LOAD_SLAB
}

// ================= final projection =================
__global__ __launch_bounds__(256) void rnn_proj(
    const float* __restrict__ wph, const float* __restrict__ bp,
    float* __restrict__ out, int src)
{
    int b = blockIdx.x;
    int tid = threadIdx.x;
    const __nv_bfloat16* Hh = g_hTh[src] + (size_t)b * HID;
    const __nv_bfloat16* Hl = g_hTl[src] + (size_t)b * HID;

    float acc[NCLS];
#pragma unroll
    for (int c = 0; c < NCLS; c++) acc[c] = 0.f;

    for (int k = tid; k < HID; k += 256) {
        float hv = __bfloat162float(Hh[k]) + __bfloat162float(Hl[k]);
#pragma unroll
        for (int c = 0; c < NCLS; c++)
            acc[c] = fmaf(wph[c * HID + k], hv, acc[c]);
    }

    __shared__ float red[256];
    for (int c = 0; c < NCLS; c++) {
        red[tid] = acc[c];
        __syncthreads();
        for (int s = 128; s > 0; s >>= 1) {
            if (tid < s) red[tid] += red[tid + s];
            __syncthreads();
        }
        if (tid == 0) out[b * NCLS + c] = red[0] + bp[c];
        __syncthreads();
    }
}

extern "C" void kernel_launch(void* const* d_in, const int* in_sizes, int n_in,
                              void* d_out, int out_size) {
    const float* x   = (const float*)d_in[0];    // [512, 128]
    const float* whx = (const float*)d_in[1];    // [2048, 1]
    const float* whh = (const float*)d_in[2];    // [2048, 2048]
    const float* bh  = (const float*)d_in[3];    // [2048, 1]
    const float* wph = (const float*)d_in[4];    // [10, 2048]
    const float* bp  = (const float*)d_in[5];    // [10, 1]
    float* out = (float*)d_out;                  // [512, 10]
    (void)in_sizes; (void)n_in; (void)out_size;

    cudaFuncSetAttribute(rnn_persist, cudaFuncAttributeMaxDynamicSharedMemorySize, SMEM_TOTAL);

    convert_w<<<(HID * HID + 255) / 256, 256>>>(whh);
    rnn_init<<<(BATCH * HID + 255) / 256, 256>>>(whx, bh, x);

    dim3 grid(HID / BN, BATCH / BM);  // (32, 4) = 128 CTAs, all co-resident
    rnn_persist<<<grid, 256, SMEM_TOTAL>>>(x, whx, bh);

    rnn_proj<<<BATCH, 256>>>(wph, bp, out, (SEQ - 1) & 1);  // final h in buf 1
}

// round 7
// speedup vs baseline: 1.3812x; 1.3468x over previous
#include <cuda_runtime.h>
#include <cuda_fp16.h>
#include <math.h>
#include <stdint.h>

#define HID 2048
#define BATCH 512
#define SEQ 128
#define NCLS 10

#define BM 128            // batch rows per CTA
#define BN 64             // hidden cols per CTA
#define KS 64             // k elements per slab
#define NSLAB (HID / KS)  // 32

#define LO_SCALE_F 2048.0f
#define LO_UNSCALE (1.0f / 2048.0f)

// ---- device globals (allocation-free scratch) ----
__device__ __half g_hT[2][BATCH * HID];   // hidden state, fp16, [B][K] row-major
__device__ __half g_Wh[HID * HID];        // whh hi (fp16), [N][K] row-major
__device__ __half g_Wl[HID * HID];        // whh residual * 2^11 (fp16)

// ---- SMEM layout (dynamic): 2-stage ----
#define SM_XS   0                 // 128 f32
#define SM_WHX  512               // 64 f32
#define SM_BH   768               // 64 f32
#define SM_SLAB 1024
#define A_OFF   0                 // 128 rows x 128B
#define WH_OFF  16384             // 64 rows x 128B
#define WL_OFF  24576
#define STAGE_SZ 32768
#define SMEM_TOTAL (SM_SLAB + 2 * STAGE_SZ)   // 66560

__device__ __forceinline__ uint32_t smem_u32(const void* p) {
    uint32_t a;
    asm("{ .reg .u64 t; cvta.to.shared.u64 t, %1; cvt.u32.u64 %0, t; }" : "=r"(a) : "l"(p));
    return a;
}
__device__ __forceinline__ void cp16(uint32_t saddr, const void* g) {
    asm volatile("cp.async.cg.shared.global [%0], [%1], 16;" :: "r"(saddr), "l"(g));
}
#define CP_COMMIT() asm volatile("cp.async.commit_group;" ::: "memory")
#define CP_WAIT(n)  asm volatile("cp.async.wait_group %0;" :: "n"(n) : "memory")

#define LDSM_X4(d0, d1, d2, d3, a) \
    asm volatile("ldmatrix.sync.aligned.m8n8.x4.shared.b16 {%0,%1,%2,%3}, [%4];" \
        : "=r"(d0), "=r"(d1), "=r"(d2), "=r"(d3) : "r"(a))

#define MMA16816F16(c0, c1, c2, c3, a0, a1, a2, a3, b0, b1) \
    asm volatile("mma.sync.aligned.m16n8k16.row.col.f32.f16.f16.f32 " \
        "{%0,%1,%2,%3}, {%4,%5,%6,%7}, {%8,%9}, {%0,%1,%2,%3};" \
        : "+f"(c0), "+f"(c1), "+f"(c2), "+f"(c3) \
        : "r"(a0), "r"(a1), "r"(a2), "r"(a3), "r"(b0), "r"(b1))

// ================= one-time prep =================
__global__ __launch_bounds__(256) void convert_w(const float* __restrict__ whh) {
    int i = blockIdx.x * blockDim.x + threadIdx.x;
    if (i >= HID * HID) return;
    float w = whh[i];
    __half hi = __float2half_rn(w);
    g_Wh[i] = hi;
    g_Wl[i] = __float2half_rn((w - __half2float(hi)) * LO_SCALE_F);
}

__global__ __launch_bounds__(256) void rnn_init(
    const float* __restrict__ whx, const float* __restrict__ bh, const float* __restrict__ x) {
    int i = blockIdx.x * blockDim.x + threadIdx.x;
    if (i >= BATCH * HID) return;
    int b = i / HID, m = i - b * HID;
    g_hT[0][i] = __float2half_rn(tanhf(whx[m] * x[b * SEQ + 0] + bh[m]));
}

// ================= per-step GEMM: hT_new = tanh(hT @ W^T + whx*x_t + bh) =================
__global__ __launch_bounds__(256, 1) void rnn_step_mma(
    const float* __restrict__ x, const float* __restrict__ whx,
    const float* __restrict__ bh, int t, int src, int dst)
{
    extern __shared__ char smem[];
    uint32_t sb = smem_u32(smem);
    int tid = threadIdx.x, wid = tid >> 5, lane = tid & 31;
    int wm = wid >> 1, wn = wid & 1;      // 4x2 warps, warp tile 32m x 32n
    int n0  = blockIdx.x * BN;            // hidden col base
    int bt0 = blockIdx.y * BM;            // batch row base

    if (tid < 128) ((float*)(smem + SM_XS))[tid] = x[(bt0 + tid) * SEQ + t];
    else if (tid < 192) ((float*)(smem + SM_WHX))[tid - 128] = whx[n0 + tid - 128];
    else ((float*)(smem + SM_BH))[tid - 192] = bh[n0 + tid - 192];

    const __half* A  = g_hT[src] + (size_t)bt0 * HID;
    const __half* Wh = g_Wh + (size_t)n0 * HID;
    const __half* Wl = g_Wl + (size_t)n0 * HID;

    float c [2][4][4];    // hi accumulator
    float c2[2][4][4];    // scaled-lo accumulator
#pragma unroll
    for (int i = 0; i < 2; i++)
#pragma unroll
        for (int j = 0; j < 4; j++)
#pragma unroll
            for (int q = 0; q < 4; q++) { c[i][j][q] = 0.f; c2[i][j][q] = 0.f; }

#define LOAD_SLAB(stage, ks) do {                                              \
        uint32_t sbase = sb + SM_SLAB + (stage) * STAGE_SZ;                    \
        _Pragma("unroll")                                                      \
        for (int i = 0; i < 4; i++) {                                          \
            int idx = tid + 256 * i; int m = idx >> 3; int cc = idx & 7;       \
            uint32_t so = (uint32_t)(m * 128) + (uint32_t)((cc ^ (m & 7)) << 4); \
            size_t go = (size_t)m * HID + (ks) * KS + cc * 8;                  \
            cp16(sbase + A_OFF + so, A + go);                                  \
        }                                                                      \
        _Pragma("unroll")                                                      \
        for (int i = 0; i < 2; i++) {                                          \
            int idx = tid + 256 * i; int n = idx >> 3; int cc = idx & 7;       \
            uint32_t so = (uint32_t)(n * 128) + (uint32_t)((cc ^ (n & 7)) << 4); \
            size_t go = (size_t)n * HID + (ks) * KS + cc * 8;                  \
            cp16(sbase + WH_OFF + so, Wh + go);                                \
            cp16(sbase + WL_OFF + so, Wl + go);                                \
        }                                                                      \
        CP_COMMIT();                                                           \
    } while (0)

    LOAD_SLAB(0, 0);

#pragma unroll 1
    for (int ks = 0; ks < NSLAB; ks++) {
        if (ks + 1 < NSLAB) {
            LOAD_SLAB((ks + 1) & 1, ks + 1);
            CP_WAIT(1);
        } else {
            CP_WAIT(0);
        }
        __syncthreads();

        uint32_t abase = sb + SM_SLAB + (ks & 1) * STAGE_SZ;
#pragma unroll
        for (int k4 = 0; k4 < 4; k4++) {
            int cb = k4 * 2;   // 16B-chunk base of this k16 within the 64-wide slab
            uint32_t ah[2][4], wh[2][4], wl[2][4];
#pragma unroll
            for (int mt = 0; mt < 2; mt++) {
                int row = wm * 32 + mt * 16 + (lane & 15);
                int ccc = cb + (lane >> 4);
                uint32_t ad = abase + A_OFF + row * 128 + ((ccc ^ (row & 7)) << 4);
                LDSM_X4(ah[mt][0], ah[mt][1], ah[mt][2], ah[mt][3], ad);
            }
#pragma unroll
            for (int nt = 0; nt < 2; nt++) {
                int row = wn * 32 + nt * 16 + (lane & 7) + ((lane >> 4) << 3);
                int ccc = cb + ((lane >> 3) & 1);
                uint32_t ad = abase + WH_OFF + row * 128 + ((ccc ^ (row & 7)) << 4);
                LDSM_X4(wh[nt][0], wh[nt][1], wh[nt][2], wh[nt][3], ad);
                LDSM_X4(wl[nt][0], wl[nt][1], wl[nt][2], wl[nt][3], ad + (WL_OFF - WH_OFF));
            }
#pragma unroll
            for (int mt = 0; mt < 2; mt++) {
#pragma unroll
                for (int j = 0; j < 4; j++) {
                    uint32_t bh0 = wh[j >> 1][(j & 1) * 2], bh1 = wh[j >> 1][(j & 1) * 2 + 1];
                    uint32_t bl0 = wl[j >> 1][(j & 1) * 2], bl1 = wl[j >> 1][(j & 1) * 2 + 1];
                    MMA16816F16(c[mt][j][0], c[mt][j][1], c[mt][j][2], c[mt][j][3],
                                ah[mt][0], ah[mt][1], ah[mt][2], ah[mt][3], bh0, bh1);
                    MMA16816F16(c2[mt][j][0], c2[mt][j][1], c2[mt][j][2], c2[mt][j][3],
                                ah[mt][0], ah[mt][1], ah[mt][2], ah[mt][3], bl0, bl1);
                }
            }
        }
        __syncthreads();
    }
#undef LOAD_SLAB

    // ---- epilogue: hi + lo*2^-11 + whx*x + bh, tanh, fp16 store ----
    const float* xs   = (const float*)(smem + SM_XS);
    const float* whxs = (const float*)(smem + SM_WHX);
    const float* bhs  = (const float*)(smem + SM_BH);
    __half* D = g_hT[dst];
    int g = lane >> 2, tg = lane & 3;

#pragma unroll
    for (int mt = 0; mt < 2; mt++) {
#pragma unroll
        for (int half = 0; half < 2; half++) {
            int rloc = wm * 32 + mt * 16 + g + half * 8;
            float xv = xs[rloc];
            size_t rowbase = (size_t)(bt0 + rloc) * HID + n0;
#pragma unroll
            for (int j = 0; j < 4; j++) {
                int nloc = wn * 32 + j * 8 + 2 * tg;
                float v0 = c[mt][j][half * 2 + 0] + c2[mt][j][half * 2 + 0] * LO_UNSCALE
                         + whxs[nloc] * xv + bhs[nloc];
                float v1 = c[mt][j][half * 2 + 1] + c2[mt][j][half * 2 + 1] * LO_UNSCALE
                         + whxs[nloc + 1] * xv + bhs[nloc + 1];
                __half2 hp = __floats2half2_rn(tanhf(v0), tanhf(v1));
                *(__half2*)(D + rowbase + nloc) = hp;
            }
        }
    }
}

// ================= final projection =================
__global__ __launch_bounds__(256) void rnn_proj(
    const float* __restrict__ wph, const float* __restrict__ bp,
    float* __restrict__ out, int src)
{
    int b = blockIdx.x;
    int tid = threadIdx.x;
    const __half* H = g_hT[src] + (size_t)b * HID;

    float acc[NCLS];
#pragma unroll
    for (int c = 0; c < NCLS; c++) acc[c] = 0.f;

    for (int k = tid; k < HID; k += 256) {
        float hv = __half2float(H[k]);
#pragma unroll
        for (int c = 0; c < NCLS; c++)
            acc[c] = fmaf(wph[c * HID + k], hv, acc[c]);
    }

    __shared__ float red[256];
    for (int c = 0; c < NCLS; c++) {
        red[tid] = acc[c];
        __syncthreads();
        for (int s = 128; s > 0; s >>= 1) {
            if (tid < s) red[tid] += red[tid + s];
            __syncthreads();
        }
        if (tid == 0) out[b * NCLS + c] = red[0] + bp[c];
        __syncthreads();
    }
}

extern "C" void kernel_launch(void* const* d_in, const int* in_sizes, int n_in,
                              void* d_out, int out_size) {
    const float* x   = (const float*)d_in[0];    // [512, 128]
    const float* whx = (const float*)d_in[1];    // [2048, 1]
    const float* whh = (const float*)d_in[2];    // [2048, 2048]
    const float* bh  = (const float*)d_in[3];    // [2048, 1]
    const float* wph = (const float*)d_in[4];    // [10, 2048]
    const float* bp  = (const float*)d_in[5];    // [10, 1]
    float* out = (float*)d_out;                  // [512, 10]
    (void)in_sizes; (void)n_in; (void)out_size;

    cudaFuncSetAttribute(rnn_step_mma, cudaFuncAttributeMaxDynamicSharedMemorySize, SMEM_TOTAL);

    convert_w<<<(HID * HID + 255) / 256, 256>>>(whh);
    rnn_init<<<(BATCH * HID + 255) / 256, 256>>>(whx, bh, x);

    dim3 grid(HID / BN, BATCH / BM);  // (32, 4) = 128 CTAs
    for (int t = 1; t < SEQ; t++) {
        rnn_step_mma<<<grid, 256, SMEM_TOTAL>>>(x, whx, bh, t, (t - 1) & 1, t & 1);
    }

    rnn_proj<<<BATCH, 256>>>(wph, bp, out, (SEQ - 1) & 1);  // final h in buf 1
}

// round 8
// speedup vs baseline: 2.1994x; 1.5924x over previous
#include <cuda_runtime.h>
#include <cuda_fp16.h>
#include <math.h>
#include <stdint.h>

#define HID 2048
#define BATCH 512
#define SEQ 128
#define NCLS 10

#define BM 128            // batch rows per CTA
#define BN 64             // hidden cols per CTA
#define KS 64             // k elements per slab
#define NSLAB (HID / KS)  // 32

// ---- device globals (allocation-free scratch) ----
__device__ __half g_hT[2][BATCH * HID];   // hidden state, fp16, [B][K] row-major
__device__ __half g_W[HID * HID];         // whh (fp16), [N][K] row-major

// ---- SMEM layout (dynamic): 2-stage ----
#define SM_XS   0                 // 128 f32
#define SM_WHX  512               // 64 f32
#define SM_BH   768               // 64 f32
#define SM_SLAB 1024
#define A_OFF   0                 // 128 rows x 128B
#define W_OFF   16384             // 64 rows x 128B
#define STAGE_SZ 24576
#define SMEM_TOTAL (SM_SLAB + 2 * STAGE_SZ)   // 50176

__device__ __forceinline__ uint32_t smem_u32(const void* p) {
    uint32_t a;
    asm("{ .reg .u64 t; cvta.to.shared.u64 t, %1; cvt.u32.u64 %0, t; }" : "=r"(a) : "l"(p));
    return a;
}
__device__ __forceinline__ void cp16(uint32_t saddr, const void* g) {
    asm volatile("cp.async.cg.shared.global [%0], [%1], 16;" :: "r"(saddr), "l"(g));
}
#define CP_COMMIT() asm volatile("cp.async.commit_group;" ::: "memory")
#define CP_WAIT(n)  asm volatile("cp.async.wait_group %0;" :: "n"(n) : "memory")

#define LDSM_X4(d0, d1, d2, d3, a) \
    asm volatile("ldmatrix.sync.aligned.m8n8.x4.shared.b16 {%0,%1,%2,%3}, [%4];" \
        : "=r"(d0), "=r"(d1), "=r"(d2), "=r"(d3) : "r"(a))

#define MMA16816F16(c0, c1, c2, c3, a0, a1, a2, a3, b0, b1) \
    asm volatile("mma.sync.aligned.m16n8k16.row.col.f32.f16.f16.f32 " \
        "{%0,%1,%2,%3}, {%4,%5,%6,%7}, {%8,%9}, {%0,%1,%2,%3};" \
        : "+f"(c0), "+f"(c1), "+f"(c2), "+f"(c3) \
        : "r"(a0), "r"(a1), "r"(a2), "r"(a3), "r"(b0), "r"(b1))

// ================= one-time prep =================
__global__ __launch_bounds__(256) void convert_w(const float* __restrict__ whh) {
    int i = blockIdx.x * blockDim.x + threadIdx.x;
    if (i >= HID * HID) return;
    g_W[i] = __float2half_rn(whh[i]);
}

__global__ __launch_bounds__(256) void rnn_init(
    const float* __restrict__ whx, const float* __restrict__ bh, const float* __restrict__ x) {
    int i = blockIdx.x * blockDim.x + threadIdx.x;
    if (i >= BATCH * HID) return;
    int b = i / HID, m = i - b * HID;
    g_hT[0][i] = __float2half_rn(tanhf(whx[m] * x[b * SEQ + 0] + bh[m]));
}

// ================= per-step GEMM: hT_new = tanh(hT @ W^T + whx*x_t + bh) =================
__global__ __launch_bounds__(256, 1) void rnn_step_mma(
    const float* __restrict__ x, const float* __restrict__ whx,
    const float* __restrict__ bh, int t, int src, int dst)
{
    extern __shared__ char smem[];
    uint32_t sb = smem_u32(smem);
    int tid = threadIdx.x, wid = tid >> 5, lane = tid & 31;
    int wm = wid >> 1, wn = wid & 1;      // 4x2 warps, warp tile 32m x 32n
    int n0  = blockIdx.x * BN;            // hidden col base
    int bt0 = blockIdx.y * BM;            // batch row base

    if (tid < 128) ((float*)(smem + SM_XS))[tid] = x[(bt0 + tid) * SEQ + t];
    else if (tid < 192) ((float*)(smem + SM_WHX))[tid - 128] = whx[n0 + tid - 128];
    else ((float*)(smem + SM_BH))[tid - 192] = bh[n0 + tid - 192];

    const __half* A = g_hT[src] + (size_t)bt0 * HID;
    const __half* W = g_W + (size_t)n0 * HID;

    float c[2][4][4];
#pragma unroll
    for (int i = 0; i < 2; i++)
#pragma unroll
        for (int j = 0; j < 4; j++)
#pragma unroll
            for (int q = 0; q < 4; q++) c[i][j][q] = 0.f;

#define LOAD_SLAB(stage, ks) do {                                              \
        uint32_t sbase = sb + SM_SLAB + (stage) * STAGE_SZ;                    \
        _Pragma("unroll")                                                      \
        for (int i = 0; i < 4; i++) {                                          \
            int idx = tid + 256 * i; int m = idx >> 3; int cc = idx & 7;       \
            uint32_t so = (uint32_t)(m * 128) + (uint32_t)((cc ^ (m & 7)) << 4); \
            size_t go = (size_t)m * HID + (ks) * KS + cc * 8;                  \
            cp16(sbase + A_OFF + so, A + go);                                  \
        }                                                                      \
        _Pragma("unroll")                                                      \
        for (int i = 0; i < 2; i++) {                                          \
            int idx = tid + 256 * i; int n = idx >> 3; int cc = idx & 7;       \
            uint32_t so = (uint32_t)(n * 128) + (uint32_t)((cc ^ (n & 7)) << 4); \
            size_t go = (size_t)n * HID + (ks) * KS + cc * 8;                  \
            cp16(sbase + W_OFF + so, W + go);                                  \
        }                                                                      \
        CP_COMMIT();                                                           \
    } while (0)

    LOAD_SLAB(0, 0);

#pragma unroll 1
    for (int ks = 0; ks < NSLAB; ks++) {
        if (ks + 1 < NSLAB) {
            LOAD_SLAB((ks + 1) & 1, ks + 1);
            CP_WAIT(1);
        } else {
            CP_WAIT(0);
        }
        __syncthreads();

        uint32_t abase = sb + SM_SLAB + (ks & 1) * STAGE_SZ;
#pragma unroll
        for (int k4 = 0; k4 < 4; k4++) {
            int cb = k4 * 2;   // 16B-chunk base of this k16 within the 64-wide slab
            uint32_t ah[2][4], wh[2][4];
#pragma unroll
            for (int mt = 0; mt < 2; mt++) {
                int row = wm * 32 + mt * 16 + (lane & 15);
                int ccc = cb + (lane >> 4);
                uint32_t ad = abase + A_OFF + row * 128 + ((ccc ^ (row & 7)) << 4);
                LDSM_X4(ah[mt][0], ah[mt][1], ah[mt][2], ah[mt][3], ad);
            }
#pragma unroll
            for (int nt = 0; nt < 2; nt++) {
                int row = wn * 32 + nt * 16 + (lane & 7) + ((lane >> 4) << 3);
                int ccc = cb + ((lane >> 3) & 1);
                uint32_t ad = abase + W_OFF + row * 128 + ((ccc ^ (row & 7)) << 4);
                LDSM_X4(wh[nt][0], wh[nt][1], wh[nt][2], wh[nt][3], ad);
            }
#pragma unroll
            for (int mt = 0; mt < 2; mt++) {
#pragma unroll
                for (int j = 0; j < 4; j++) {
                    uint32_t b0 = wh[j >> 1][(j & 1) * 2], b1 = wh[j >> 1][(j & 1) * 2 + 1];
                    MMA16816F16(c[mt][j][0], c[mt][j][1], c[mt][j][2], c[mt][j][3],
                                ah[mt][0], ah[mt][1], ah[mt][2], ah[mt][3], b0, b1);
                }
            }
        }
        __syncthreads();
    }
#undef LOAD_SLAB

    // ---- epilogue: + whx*x + bh, tanh, fp16 store ----
    const float* xs   = (const float*)(smem + SM_XS);
    const float* whxs = (const float*)(smem + SM_WHX);
    const float* bhs  = (const float*)(smem + SM_BH);
    __half* D = g_hT[dst];
    int g = lane >> 2, tg = lane & 3;

#pragma unroll
    for (int mt = 0; mt < 2; mt++) {
#pragma unroll
        for (int half = 0; half < 2; half++) {
            int rloc = wm * 32 + mt * 16 + g + half * 8;
            float xv = xs[rloc];
            size_t rowbase = (size_t)(bt0 + rloc) * HID + n0;
#pragma unroll
            for (int j = 0; j < 4; j++) {
                int nloc = wn * 32 + j * 8 + 2 * tg;
                float v0 = c[mt][j][half * 2 + 0] + whxs[nloc] * xv + bhs[nloc];
                float v1 = c[mt][j][half * 2 + 1] + whxs[nloc + 1] * xv + bhs[nloc + 1];
                __half2 hp = __floats2half2_rn(tanhf(v0), tanhf(v1));
                *(__half2*)(D + rowbase + nloc) = hp;
            }
        }
    }
}

// ================= final projection: one warp per batch row =================
__global__ __launch_bounds__(256) void rnn_proj(
    const float* __restrict__ wph, const float* __restrict__ bp,
    float* __restrict__ out, int src)
{
    int wid = threadIdx.x >> 5, lane = threadIdx.x & 31;
    int b = blockIdx.x * 8 + wid;          // 64 blocks x 8 warps = 512 batches
    const __half2* H = (const __half2*)(g_hT[src] + (size_t)b * HID);

    float acc[NCLS];
#pragma unroll
    for (int c = 0; c < NCLS; c++) acc[c] = 0.f;

#pragma unroll 4
    for (int k2 = lane; k2 < HID / 2; k2 += 32) {
        float2 hv = __half22float2(H[k2]);
#pragma unroll
        for (int c = 0; c < NCLS; c++) {
            const float2 w = *(const float2*)(wph + c * HID + k2 * 2);
            acc[c] = fmaf(w.x, hv.x, fmaf(w.y, hv.y, acc[c]));
        }
    }
#pragma unroll
    for (int c = 0; c < NCLS; c++) {
#pragma unroll
        for (int s = 16; s > 0; s >>= 1)
            acc[c] += __shfl_xor_sync(0xFFFFFFFFu, acc[c], s);
    }
    if (lane < NCLS) out[b * NCLS + lane] = acc[lane] + bp[lane];
}

extern "C" void kernel_launch(void* const* d_in, const int* in_sizes, int n_in,
                              void* d_out, int out_size) {
    const float* x   = (const float*)d_in[0];    // [512, 128]
    const float* whx = (const float*)d_in[1];    // [2048, 1]
    const float* whh = (const float*)d_in[2];    // [2048, 2048]
    const float* bh  = (const float*)d_in[3];    // [2048, 1]
    const float* wph = (const float*)d_in[4];    // [10, 2048]
    const float* bp  = (const float*)d_in[5];    // [10, 1]
    float* out = (float*)d_out;                  // [512, 10]
    (void)in_sizes; (void)n_in; (void)out_size;

    cudaFuncSetAttribute(rnn_step_mma, cudaFuncAttributeMaxDynamicSharedMemorySize, SMEM_TOTAL);

    convert_w<<<(HID * HID + 255) / 256, 256>>>(whh);
    rnn_init<<<(BATCH * HID + 255) / 256, 256>>>(whx, bh, x);

    dim3 grid(HID / BN, BATCH / BM);  // (32, 4) = 128 CTAs
    for (int t = 1; t < SEQ; t++) {
        rnn_step_mma<<<grid, 256, SMEM_TOTAL>>>(x, whx, bh, t, (t - 1) & 1, t & 1);
    }

    rnn_proj<<<BATCH / 8, 256>>>(wph, bp, out, (SEQ - 1) & 1);  // final h in buf 1
}

// round 9
// speedup vs baseline: 2.4239x; 1.1020x over previous
#include <cuda_runtime.h>
#include <cuda_fp16.h>
#include <math.h>
#include <stdint.h>

#define HID 2048
#define BATCH 512
#define SEQ 128
#define NCLS 10

#define BM 128             // batch rows per CTA
#define BN 64              // hidden cols per CTA
#define KS 128             // k elements per slab
#define NSLAB (HID / KS)   // 16

// ---- device globals (allocation-free scratch) ----
__device__ __half g_hT[2][BATCH * HID];   // hidden state, fp16, [B][K] row-major
__device__ __half g_W[HID * HID];         // whh (fp16), [N][K] row-major

// ---- SMEM layout (dynamic): 2-stage, each stage = A[2 halves] + W[2 halves] ----
#define SM_XS   0                 // 128 f32
#define SM_WHX  512               // 64 f32
#define SM_BH   768               // 64 f32
#define SM_SLAB 1024
#define A_OFF   0                 // [khalf][128 rows][128B]  -> 2 x 16384
#define W_OFF   32768             // [khalf][64 rows][128B]   -> 2 x 8192
#define STAGE_SZ 49152
#define SMEM_TOTAL (SM_SLAB + 2 * STAGE_SZ)   // 99328

__device__ __forceinline__ uint32_t smem_u32(const void* p) {
    uint32_t a;
    asm("{ .reg .u64 t; cvta.to.shared.u64 t, %1; cvt.u32.u64 %0, t; }" : "=r"(a) : "l"(p));
    return a;
}
__device__ __forceinline__ void cp16(uint32_t saddr, const void* g) {
    asm volatile("cp.async.cg.shared.global [%0], [%1], 16;" :: "r"(saddr), "l"(g));
}
#define CP_COMMIT() asm volatile("cp.async.commit_group;" ::: "memory")
#define CP_WAIT(n)  asm volatile("cp.async.wait_group %0;" :: "n"(n) : "memory")

#define LDSM_X4(d0, d1, d2, d3, a) \
    asm volatile("ldmatrix.sync.aligned.m8n8.x4.shared.b16 {%0,%1,%2,%3}, [%4];" \
        : "=r"(d0), "=r"(d1), "=r"(d2), "=r"(d3) : "r"(a))

#define MMA16816F16(c0, c1, c2, c3, a0, a1, a2, a3, b0, b1) \
    asm volatile("mma.sync.aligned.m16n8k16.row.col.f32.f16.f16.f32 " \
        "{%0,%1,%2,%3}, {%4,%5,%6,%7}, {%8,%9}, {%0,%1,%2,%3};" \
        : "+f"(c0), "+f"(c1), "+f"(c2), "+f"(c3) \
        : "r"(a0), "r"(a1), "r"(a2), "r"(a3), "r"(b0), "r"(b1))

// ================= one-time prep =================
__global__ __launch_bounds__(256) void convert_w(const float* __restrict__ whh) {
    int i = blockIdx.x * blockDim.x + threadIdx.x;
    if (i >= HID * HID) return;
    g_W[i] = __float2half_rn(whh[i]);
}

__global__ __launch_bounds__(256) void rnn_init(
    const float* __restrict__ whx, const float* __restrict__ bh, const float* __restrict__ x) {
    int i = blockIdx.x * blockDim.x + threadIdx.x;
    if (i >= BATCH * HID) return;
    int b = i / HID, m = i - b * HID;
    g_hT[0][i] = __float2half_rn(tanhf(whx[m] * x[b * SEQ + 0] + bh[m]));
}

// ================= per-step GEMM: hT_new = tanh(hT @ W^T + whx*x_t + bh) =================
__global__ __launch_bounds__(256, 1) void rnn_step_mma(
    const float* __restrict__ x, const float* __restrict__ whx,
    const float* __restrict__ bh, int t, int src, int dst)
{
    extern __shared__ char smem[];
    uint32_t sb = smem_u32(smem);
    int tid = threadIdx.x, wid = tid >> 5, lane = tid & 31;
    int wm = wid >> 1, wn = wid & 1;      // 4x2 warps, warp tile 32m x 32n
    int n0  = blockIdx.x * BN;            // hidden col base
    int bt0 = blockIdx.y * BM;            // batch row base

    if (tid < 128) ((float*)(smem + SM_XS))[tid] = x[(bt0 + tid) * SEQ + t];
    else if (tid < 192) ((float*)(smem + SM_WHX))[tid - 128] = whx[n0 + tid - 128];
    else ((float*)(smem + SM_BH))[tid - 192] = bh[n0 + tid - 192];

    const __half* A = g_hT[src] + (size_t)bt0 * HID;
    const __half* W = g_W + (size_t)n0 * HID;

    float c[2][4][4];
#pragma unroll
    for (int i = 0; i < 2; i++)
#pragma unroll
        for (int j = 0; j < 4; j++)
#pragma unroll
            for (int q = 0; q < 4; q++) c[i][j][q] = 0.f;

    // precomputed fragment address components (stage-independent parts)
    int a_row[2], w_row[2];
#pragma unroll
    for (int mt = 0; mt < 2; mt++) a_row[mt] = wm * 32 + mt * 16 + (lane & 15);
#pragma unroll
    for (int nt = 0; nt < 2; nt++) w_row[nt] = wn * 32 + nt * 16 + (lane & 7) + ((lane >> 4) << 3);
    int a_cadd = lane >> 4;          // chunk offset within k16 for A
    int w_cadd = (lane >> 3) & 1;    // chunk offset within k16 for W

#define LOAD_SLAB(stage, ks) do {                                                \
        uint32_t sbase = sb + SM_SLAB + (stage) * STAGE_SZ;                      \
        _Pragma("unroll")                                                        \
        for (int h = 0; h < 2; h++) {                                            \
            _Pragma("unroll")                                                    \
            for (int i = 0; i < 4; i++) {                                        \
                int idx = tid + 256 * i; int m = idx >> 3; int cc = idx & 7;     \
                uint32_t so = (uint32_t)(m * 128) + (uint32_t)((cc ^ (m & 7)) << 4); \
                size_t go = (size_t)m * HID + (ks) * KS + h * 64 + cc * 8;       \
                cp16(sbase + A_OFF + h * 16384 + so, A + go);                    \
            }                                                                    \
            _Pragma("unroll")                                                    \
            for (int i = 0; i < 2; i++) {                                        \
                int idx = tid + 256 * i; int n = idx >> 3; int cc = idx & 7;     \
                uint32_t so = (uint32_t)(n * 128) + (uint32_t)((cc ^ (n & 7)) << 4); \
                size_t go = (size_t)n * HID + (ks) * KS + h * 64 + cc * 8;       \
                cp16(sbase + W_OFF + h * 8192 + so, W + go);                     \
            }                                                                    \
        }                                                                        \
        CP_COMMIT();                                                             \
    } while (0)

// load ldmatrix fragments for k16-iter kq (0..7) of the slab at abase into buffer bb
#define LD_FRAGS(bb, abase, kq) do {                                             \
        int khalf = (kq) >> 2; int cb = ((kq) & 3) * 2;                          \
        _Pragma("unroll")                                                        \
        for (int mt = 0; mt < 2; mt++) {                                         \
            int ccc = cb + a_cadd;                                               \
            uint32_t ad = (abase) + A_OFF + khalf * 16384 + a_row[mt] * 128      \
                        + ((ccc ^ (a_row[mt] & 7)) << 4);                        \
            LDSM_X4(ah[bb][mt][0], ah[bb][mt][1], ah[bb][mt][2], ah[bb][mt][3], ad); \
        }                                                                        \
        _Pragma("unroll")                                                        \
        for (int nt = 0; nt < 2; nt++) {                                         \
            int ccc = cb + w_cadd;                                               \
            uint32_t ad = (abase) + W_OFF + khalf * 8192 + w_row[nt] * 128       \
                        + ((ccc ^ (w_row[nt] & 7)) << 4);                        \
            LDSM_X4(wh[bb][nt][0], wh[bb][nt][1], wh[bb][nt][2], wh[bb][nt][3], ad); \
        }                                                                        \
    } while (0)

    LOAD_SLAB(0, 0);

    uint32_t ah[2][2][4], wh[2][2][4];

#pragma unroll 1
    for (int ks = 0; ks < NSLAB; ks++) {
        if (ks + 1 < NSLAB) {
            LOAD_SLAB((ks + 1) & 1, ks + 1);
            CP_WAIT(1);
        } else {
            CP_WAIT(0);
        }
        __syncthreads();

        uint32_t abase = sb + SM_SLAB + (ks & 1) * STAGE_SZ;
        LD_FRAGS(0, abase, 0);
#pragma unroll
        for (int kq = 0; kq < 8; kq++) {
            if (kq < 7) LD_FRAGS((kq + 1) & 1, abase, kq + 1);
            int bb = kq & 1;
#pragma unroll
            for (int mt = 0; mt < 2; mt++) {
#pragma unroll
                for (int j = 0; j < 4; j++) {
                    uint32_t b0 = wh[bb][j >> 1][(j & 1) * 2];
                    uint32_t b1 = wh[bb][j >> 1][(j & 1) * 2 + 1];
                    MMA16816F16(c[mt][j][0], c[mt][j][1], c[mt][j][2], c[mt][j][3],
                                ah[bb][mt][0], ah[bb][mt][1], ah[bb][mt][2], ah[bb][mt][3],
                                b0, b1);
                }
            }
        }
        __syncthreads();
    }
#undef LOAD_SLAB
#undef LD_FRAGS

    // ---- epilogue: + whx*x + bh, tanh, fp16 store ----
    const float* xs   = (const float*)(smem + SM_XS);
    const float* whxs = (const float*)(smem + SM_WHX);
    const float* bhs  = (const float*)(smem + SM_BH);
    __half* D = g_hT[dst];
    int g = lane >> 2, tg = lane & 3;

#pragma unroll
    for (int mt = 0; mt < 2; mt++) {
#pragma unroll
        for (int half = 0; half < 2; half++) {
            int rloc = wm * 32 + mt * 16 + g + half * 8;
            float xv = xs[rloc];
            size_t rowbase = (size_t)(bt0 + rloc) * HID + n0;
#pragma unroll
            for (int j = 0; j < 4; j++) {
                int nloc = wn * 32 + j * 8 + 2 * tg;
                float v0 = c[mt][j][half * 2 + 0] + whxs[nloc] * xv + bhs[nloc];
                float v1 = c[mt][j][half * 2 + 1] + whxs[nloc + 1] * xv + bhs[nloc + 1];
                __half2 hp = __floats2half2_rn(tanhf(v0), tanhf(v1));
                *(__half2*)(D + rowbase + nloc) = hp;
            }
        }
    }
}

// ================= final projection: one warp per batch row =================
__global__ __launch_bounds__(256) void rnn_proj(
    const float* __restrict__ wph, const float* __restrict__ bp,
    float* __restrict__ out, int src)
{
    int wid = threadIdx.x >> 5, lane = threadIdx.x & 31;
    int b = blockIdx.x * 8 + wid;          // 64 blocks x 8 warps = 512 batches
    const __half2* H = (const __half2*)(g_hT[src] + (size_t)b * HID);

    float acc[NCLS];
#pragma unroll
    for (int c = 0; c < NCLS; c++) acc[c] = 0.f;

#pragma unroll 4
    for (int k2 = lane; k2 < HID / 2; k2 += 32) {
        float2 hv = __half22float2(H[k2]);
#pragma unroll
        for (int c = 0; c < NCLS; c++) {
            const float2 w = *(const float2*)(wph + c * HID + k2 * 2);
            acc[c] = fmaf(w.x, hv.x, fmaf(w.y, hv.y, acc[c]));
        }
    }
#pragma unroll
    for (int c = 0; c < NCLS; c++) {
#pragma unroll
        for (int s = 16; s > 0; s >>= 1)
            acc[c] += __shfl_xor_sync(0xFFFFFFFFu, acc[c], s);
    }
    if (lane < NCLS) out[b * NCLS + lane] = acc[lane] + bp[lane];
}

extern "C" void kernel_launch(void* const* d_in, const int* in_sizes, int n_in,
                              void* d_out, int out_size) {
    const float* x   = (const float*)d_in[0];    // [512, 128]
    const float* whx = (const float*)d_in[1];    // [2048, 1]
    const float* whh = (const float*)d_in[2];    // [2048, 2048]
    const float* bh  = (const float*)d_in[3];    // [2048, 1]
    const float* wph = (const float*)d_in[4];    // [10, 2048]
    const float* bp  = (const float*)d_in[5];    // [10, 1]
    float* out = (float*)d_out;                  // [512, 10]
    (void)in_sizes; (void)n_in; (void)out_size;

    cudaFuncSetAttribute(rnn_step_mma, cudaFuncAttributeMaxDynamicSharedMemorySize, SMEM_TOTAL);

    convert_w<<<(HID * HID + 255) / 256, 256>>>(whh);
    rnn_init<<<(BATCH * HID + 255) / 256, 256>>>(whx, bh, x);

    dim3 grid(HID / BN, BATCH / BM);  // (32, 4) = 128 CTAs
    for (int t = 1; t < SEQ; t++) {
        rnn_step_mma<<<grid, 256, SMEM_TOTAL>>>(x, whx, bh, t, (t - 1) & 1, t & 1);
    }

    rnn_proj<<<BATCH / 8, 256>>>(wph, bp, out, (SEQ - 1) & 1);  // final h in buf 1
}

// round 10
// speedup vs baseline: 2.5291x; 1.0434x over previous
#include <cuda_runtime.h>
#include <cuda_fp16.h>
#include <math.h>
#include <stdint.h>

#define HID 2048
#define BATCH 512
#define SEQ 128
#define NCLS 10

#define BM 64              // batch rows per CTA
#define BN 64              // hidden cols per CTA
#define KS 128             // k elements per slab
#define NSLAB (HID / KS)   // 16
#define NTHR 128           // 4 warps

// ---- device globals (allocation-free scratch) ----
__device__ __half g_hT[2][BATCH * HID];   // hidden state, fp16, [B][K] row-major
__device__ __half g_W[HID * HID];         // whh (fp16), [N][K] row-major

// ---- SMEM layout (dynamic): 2-stage, each stage = A[2 khalves] + W[2 khalves] ----
#define SM_XS   0                 // 64 f32
#define SM_WHX  256               // 64 f32
#define SM_BH   512               // 64 f32
#define SM_SLAB 1024
#define A_OFF   0                 // [khalf][64 rows][128B]  -> 2 x 8192
#define W_OFF   16384             // [khalf][64 rows][128B]  -> 2 x 8192
#define STAGE_SZ 32768
#define SMEM_TOTAL (SM_SLAB + 2 * STAGE_SZ)   // 66560

__device__ __forceinline__ uint32_t smem_u32(const void* p) {
    uint32_t a;
    asm("{ .reg .u64 t; cvta.to.shared.u64 t, %1; cvt.u32.u64 %0, t; }" : "=r"(a) : "l"(p));
    return a;
}
__device__ __forceinline__ void cp16(uint32_t saddr, const void* g) {
    asm volatile("cp.async.cg.shared.global [%0], [%1], 16;" :: "r"(saddr), "l"(g));
}
#define CP_COMMIT() asm volatile("cp.async.commit_group;" ::: "memory")
#define CP_WAIT(n)  asm volatile("cp.async.wait_group %0;" :: "n"(n) : "memory")

#define LDSM_X4(d0, d1, d2, d3, a) \
    asm volatile("ldmatrix.sync.aligned.m8n8.x4.shared.b16 {%0,%1,%2,%3}, [%4];" \
        : "=r"(d0), "=r"(d1), "=r"(d2), "=r"(d3) : "r"(a))

#define MMA16816F16(c0, c1, c2, c3, a0, a1, a2, a3, b0, b1) \
    asm volatile("mma.sync.aligned.m16n8k16.row.col.f32.f16.f16.f32 " \
        "{%0,%1,%2,%3}, {%4,%5,%6,%7}, {%8,%9}, {%0,%1,%2,%3};" \
        : "+f"(c0), "+f"(c1), "+f"(c2), "+f"(c3) \
        : "r"(a0), "r"(a1), "r"(a2), "r"(a3), "r"(b0), "r"(b1))

// ================= one-time prep =================
__global__ __launch_bounds__(256) void convert_w(const float* __restrict__ whh) {
    int i = blockIdx.x * blockDim.x + threadIdx.x;
    if (i >= HID * HID) return;
    g_W[i] = __float2half_rn(whh[i]);
}

__global__ __launch_bounds__(256) void rnn_init(
    const float* __restrict__ whx, const float* __restrict__ bh, const float* __restrict__ x) {
    int i = blockIdx.x * blockDim.x + threadIdx.x;
    if (i >= BATCH * HID) return;
    int b = i / HID, m = i - b * HID;
    g_hT[0][i] = __float2half_rn(tanhf(whx[m] * x[b * SEQ + 0] + bh[m]));
}

// ================= per-step GEMM: hT_new = tanh(hT @ W^T + whx*x_t + bh) =================
__global__ __launch_bounds__(NTHR, 2) void rnn_step_mma(
    const float* __restrict__ x, const float* __restrict__ whx,
    const float* __restrict__ bh, int t, int src, int dst)
{
    extern __shared__ char smem[];
    uint32_t sb = smem_u32(smem);
    int tid = threadIdx.x, wid = tid >> 5, lane = tid & 31;
    int wm = wid >> 1, wn = wid & 1;      // 2x2 warps, warp tile 32m x 32n
    int n0  = blockIdx.x * BN;            // hidden col base
    int bt0 = blockIdx.y * BM;            // batch row base

    if (tid < 64) {
        ((float*)(smem + SM_XS))[tid] = x[(bt0 + tid) * SEQ + t];
    } else {
        ((float*)(smem + SM_WHX))[tid - 64] = whx[n0 + tid - 64];
        ((float*)(smem + SM_BH))[tid - 64]  = bh[n0 + tid - 64];
    }

    const __half* A = g_hT[src] + (size_t)bt0 * HID;
    const __half* W = g_W + (size_t)n0 * HID;

    float c[2][4][4];
#pragma unroll
    for (int i = 0; i < 2; i++)
#pragma unroll
        for (int j = 0; j < 4; j++)
#pragma unroll
            for (int q = 0; q < 4; q++) c[i][j][q] = 0.f;

    // fragment address components (stage-independent)
    int a_row[2], w_row[2];
#pragma unroll
    for (int mt = 0; mt < 2; mt++) a_row[mt] = wm * 32 + mt * 16 + (lane & 15);
#pragma unroll
    for (int nt = 0; nt < 2; nt++) w_row[nt] = wn * 32 + nt * 16 + (lane & 7) + ((lane >> 4) << 3);
    int a_cadd = lane >> 4;          // chunk offset within k16 for A
    int w_cadd = (lane >> 3) & 1;    // chunk offset within k16 for W

#define LOAD_SLAB(stage, ks) do {                                                \
        uint32_t sbase = sb + SM_SLAB + (stage) * STAGE_SZ;                      \
        _Pragma("unroll")                                                        \
        for (int h = 0; h < 2; h++) {                                            \
            _Pragma("unroll")                                                    \
            for (int i = 0; i < 4; i++) {                                        \
                int idx = tid + NTHR * i; int m = idx >> 3; int cc = idx & 7;    \
                uint32_t so = (uint32_t)(m * 128) + (uint32_t)((cc ^ (m & 7)) << 4); \
                size_t go = (size_t)m * HID + (ks) * KS + h * 64 + cc * 8;       \
                cp16(sbase + A_OFF + h * 8192 + so, A + go);                     \
            }                                                                    \
            _Pragma("unroll")                                                    \
            for (int i = 0; i < 4; i++) {                                        \
                int idx = tid + NTHR * i; int n = idx >> 3; int cc = idx & 7;    \
                uint32_t so = (uint32_t)(n * 128) + (uint32_t)((cc ^ (n & 7)) << 4); \
                size_t go = (size_t)n * HID + (ks) * KS + h * 64 + cc * 8;       \
                cp16(sbase + W_OFF + h * 8192 + so, W + go);                     \
            }                                                                    \
        }                                                                        \
        CP_COMMIT();                                                             \
    } while (0)

// load ldmatrix fragments for k16-iter kq (0..7) of the slab at abase into buffer bb
#define LD_FRAGS(bb, abase, kq) do {                                             \
        int khalf = (kq) >> 2; int cb = ((kq) & 3) * 2;                          \
        _Pragma("unroll")                                                        \
        for (int mt = 0; mt < 2; mt++) {                                         \
            int ccc = cb + a_cadd;                                               \
            uint32_t ad = (abase) + A_OFF + khalf * 8192 + a_row[mt] * 128       \
                        + ((ccc ^ (a_row[mt] & 7)) << 4);                        \
            LDSM_X4(ah[bb][mt][0], ah[bb][mt][1], ah[bb][mt][2], ah[bb][mt][3], ad); \
        }                                                                        \
        _Pragma("unroll")                                                        \
        for (int nt = 0; nt < 2; nt++) {                                         \
            int ccc = cb + w_cadd;                                               \
            uint32_t ad = (abase) + W_OFF + khalf * 8192 + w_row[nt] * 128       \
                        + ((ccc ^ (w_row[nt] & 7)) << 4);                        \
            LDSM_X4(wh[bb][nt][0], wh[bb][nt][1], wh[bb][nt][2], wh[bb][nt][3], ad); \
        }                                                                        \
    } while (0)

    LOAD_SLAB(0, 0);

    uint32_t ah[2][2][4], wh[2][2][4];

#pragma unroll 1
    for (int ks = 0; ks < NSLAB; ks++) {
        if (ks + 1 < NSLAB) {
            LOAD_SLAB((ks + 1) & 1, ks + 1);
            CP_WAIT(1);
        } else {
            CP_WAIT(0);
        }
        __syncthreads();

        uint32_t abase = sb + SM_SLAB + (ks & 1) * STAGE_SZ;
        LD_FRAGS(0, abase, 0);
#pragma unroll
        for (int kq = 0; kq < 8; kq++) {
            if (kq < 7) LD_FRAGS((kq + 1) & 1, abase, kq + 1);
            int bb = kq & 1;
#pragma unroll
            for (int mt = 0; mt < 2; mt++) {
#pragma unroll
                for (int j = 0; j < 4; j++) {
                    uint32_t b0 = wh[bb][j >> 1][(j & 1) * 2];
                    uint32_t b1 = wh[bb][j >> 1][(j & 1) * 2 + 1];
                    MMA16816F16(c[mt][j][0], c[mt][j][1], c[mt][j][2], c[mt][j][3],
                                ah[bb][mt][0], ah[bb][mt][1], ah[bb][mt][2], ah[bb][mt][3],
                                b0, b1);
                }
            }
        }
        __syncthreads();
    }
#undef LOAD_SLAB
#undef LD_FRAGS

    // ---- epilogue: + whx*x + bh, tanh, fp16 store ----
    const float* xs   = (const float*)(smem + SM_XS);
    const float* whxs = (const float*)(smem + SM_WHX);
    const float* bhs  = (const float*)(smem + SM_BH);
    __half* D = g_hT[dst];
    int g = lane >> 2, tg = lane & 3;

#pragma unroll
    for (int mt = 0; mt < 2; mt++) {
#pragma unroll
        for (int half = 0; half < 2; half++) {
            int rloc = wm * 32 + mt * 16 + g + half * 8;
            float xv = xs[rloc];
            size_t rowbase = (size_t)(bt0 + rloc) * HID + n0;
#pragma unroll
            for (int j = 0; j < 4; j++) {
                int nloc = wn * 32 + j * 8 + 2 * tg;
                float v0 = c[mt][j][half * 2 + 0] + whxs[nloc] * xv + bhs[nloc];
                float v1 = c[mt][j][half * 2 + 1] + whxs[nloc + 1] * xv + bhs[nloc + 1];
                __half2 hp = __floats2half2_rn(tanhf(v0), tanhf(v1));
                *(__half2*)(D + rowbase + nloc) = hp;
            }
        }
    }
}

// ================= final projection: one warp per batch row =================
__global__ __launch_bounds__(256) void rnn_proj(
    const float* __restrict__ wph, const float* __restrict__ bp,
    float* __restrict__ out, int src)
{
    int wid = threadIdx.x >> 5, lane = threadIdx.x & 31;
    int b = blockIdx.x * 8 + wid;          // 64 blocks x 8 warps = 512 batches
    const __half2* H = (const __half2*)(g_hT[src] + (size_t)b * HID);

    float acc[NCLS];
#pragma unroll
    for (int c = 0; c < NCLS; c++) acc[c] = 0.f;

#pragma unroll 4
    for (int k2 = lane; k2 < HID / 2; k2 += 32) {
        float2 hv = __half22float2(H[k2]);
#pragma unroll
        for (int c = 0; c < NCLS; c++) {
            const float2 w = *(const float2*)(wph + c * HID + k2 * 2);
            acc[c] = fmaf(w.x, hv.x, fmaf(w.y, hv.y, acc[c]));
        }
    }
#pragma unroll
    for (int c = 0; c < NCLS; c++) {
#pragma unroll
        for (int s = 16; s > 0; s >>= 1)
            acc[c] += __shfl_xor_sync(0xFFFFFFFFu, acc[c], s);
    }
    if (lane < NCLS) out[b * NCLS + lane] = acc[lane] + bp[lane];
}

extern "C" void kernel_launch(void* const* d_in, const int* in_sizes, int n_in,
                              void* d_out, int out_size) {
    const float* x   = (const float*)d_in[0];    // [512, 128]
    const float* whx = (const float*)d_in[1];    // [2048, 1]
    const float* whh = (const float*)d_in[2];    // [2048, 2048]
    const float* bh  = (const float*)d_in[3];    // [2048, 1]
    const float* wph = (const float*)d_in[4];    // [10, 2048]
    const float* bp  = (const float*)d_in[5];    // [10, 1]
    float* out = (float*)d_out;                  // [512, 10]
    (void)in_sizes; (void)n_in; (void)out_size;

    cudaFuncSetAttribute(rnn_step_mma, cudaFuncAttributeMaxDynamicSharedMemorySize, SMEM_TOTAL);

    convert_w<<<(HID * HID + 255) / 256, 256>>>(whh);
    rnn_init<<<(BATCH * HID + 255) / 256, 256>>>(whx, bh, x);

    dim3 grid(HID / BN, BATCH / BM);  // (32, 8) = 256 CTAs -> 2 CTAs/SM
    for (int t = 1; t < SEQ; t++) {
        rnn_step_mma<<<grid, NTHR, SMEM_TOTAL>>>(x, whx, bh, t, (t - 1) & 1, t & 1);
    }

    rnn_proj<<<BATCH / 8, 256>>>(wph, bp, out, (SEQ - 1) & 1);  // final h in buf 1
}